// round 7
// baseline (speedup 1.0000x reference)
#include <cuda_runtime.h>

// Problem-instance capacities. Scratch is __device__ global (allocation-guard safe).
#define NK_CAP  2048
#define DIM_CAP 512
#define S_CAP   131072

__device__ float  g_cT[(size_t)NK_CAP * DIM_CAP];  // c transposed: [NK][DIM], 4 MB
__device__ float4 g_w4[S_CAP];                     // per-sample weights
__device__ int    g_c0[S_CAP];                     // per-sample first column

// ---------------------------------------------------------------------------
// Kernel 1: transpose c[DIM][NK] -> g_cT[NK][DIM] (tiled, conflict-free)
// ---------------------------------------------------------------------------
__global__ void bspline_transpose(const float* __restrict__ c, int DIM, int NK) {
    __shared__ float tile[32][33];
    const int x  = blockIdx.x * 32 + threadIdx.x;  // knot index (c column)
    const int y0 = blockIdx.y * 32;                // dim base   (c row)
    #pragma unroll
    for (int i = threadIdx.y; i < 32; i += 8) {
        int y = y0 + i;
        if (x < NK && y < DIM)
            tile[i][threadIdx.x] = c[(size_t)y * NK + x];
    }
    __syncthreads();
    const int xd  = y0 + threadIdx.x;              // dim index (cT column)
    const int yk0 = blockIdx.x * 32;               // knot base (cT row)
    #pragma unroll
    for (int i = threadIdx.y; i < 32; i += 8) {
        int yk = yk0 + i;
        if (xd < DIM && yk < NK)
            g_cT[(size_t)yk * DIM + xd] = tile[threadIdx.x][i];
    }
}

// ---------------------------------------------------------------------------
// Kernel 2: one thread per sample — binary search + 4 Cox-de Boor weights.
// All threads search in parallel (no serialization, no barrier).
// Faithful to the reference's truncated in-place recursion:
//   final row F[i] = B3[i] (i < NK-3), B2[NK-3], B1[NK-2], B0[NK-1];
//   samples beyond the last proper span give an all-zero row;
//   denom==0 -> weight 0.
// ---------------------------------------------------------------------------
__global__ __launch_bounds__(256)
void bspline_weights(const float* __restrict__ t,
                     const int*   __restrict__ delta_raw,
                     float* __restrict__ out,
                     int NK, int S, int sp_count) {
    const int sidx = blockIdx.x * 256 + threadIdx.x;
    if (sidx >= S) return;

    // delta arrives as int32 (python int); tolerate float32 encoding too.
    int iv = *delta_raw;
    float delta = (iv > 0 && iv < (1 << 20)) ? (float)iv : __int_as_float(iv);

    const float s = (float)sidx * delta;
    if (sp_count) out[sidx] = s;  // sample_points region

    float w0 = 0.f, w1 = 0.f, w2 = 0.f, w3 = 0.f;
    int c0 = 0;

    // ub = first index with t[ub] > s  (span j = ub + 3 in padded knots)
    int lo = 0, hi = NK;
    while (lo < hi) {
        int mid = (lo + hi) >> 1;
        if (__ldg(&t[mid]) > s) hi = mid; else lo = mid + 1;
    }
    const int ub = lo;
    if (ub <= NK - 4) {
        const int j = ub + 3;  // padded-knot span: k[j] <= s < k[j+1]
        float k[8];
        #pragma unroll
        for (int m = 1; m <= 6; m++) {
            int gi = j - 3 + m;
            k[m] = (gi < 4) ? 0.0f : __ldg(&t[gi - 4]);
        }
        const float Km2 = k[1], Km1 = k[2], K0 = k[3];
        const float K1  = k[4], K2  = k[5], K3 = k[6];

        auto rat = [](float num, float den) -> float {
            return (den == 0.0f) ? 0.0f : num / den;
        };

        // degree 1
        const float b1a = rat(K1 - s, K1 - K0);
        const float b1b = rat(s - K0, K1 - K0);
        // degree 2
        const float b2a = rat(K1 - s, K1 - Km1) * b1a;
        const float b2b = rat(s - Km1, K1 - Km1) * b1a
                        + rat(K2 - s, K2 - K0)   * b1b;
        const float b2c = rat(s - K0, K2 - K0)   * b1b;
        // degree 3
        const float b3a = rat(K1 - s, K1 - Km2) * b2a;
        const float b3b = rat(s - Km2, K1 - Km2) * b2a
                        + rat(K2 - s, K2 - Km1)  * b2b;
        const float b3c = rat(s - Km1, K2 - Km1) * b2b
                        + rat(K3 - s, K3 - K0)   * b2c;
        const float b3d = rat(s - K0, K3 - K0)   * b2c;

        const float b3v[4] = {b3a, b3b, b3c, b3d};
        const float b2v[3] = {b2a, b2b, b2c};
        const float b1v[2] = {b1a, b1b};
        float wv[4];
        #pragma unroll
        for (int m = 0; m < 4; m++) {
            const int col = j - 3 + m;
            float f = b3v[m];                                    // proper deg-3
            if (col == NK - 3)      f = b2v[m > 0 ? m - 1 : 0];  // stale deg-2
            else if (col == NK - 2) f = b1v[m > 1 ? m - 2 : 0];  // stale deg-1
            else if (col == NK - 1) f = 1.0f;                    // stale deg-0
            wv[m] = f;
        }
        w0 = wv[0]; w1 = wv[1]; w2 = wv[2]; w3 = wv[3];
        c0 = j - 3;
    }
    g_w4[sidx] = make_float4(w0, w1, w2, w3);
    g_c0[sidx] = c0;
}

// ---------------------------------------------------------------------------
// Kernel 3 (fast path): pure streaming epilogue. One thread produces TWO
// float4 outputs of one sample (dims d and d + DIM4/2). 8 independent
// LDG.128 + 2 STG.128 per thread -> deep MLP, no barriers, no shared mem.
// Requires DIM4 = DIM/4 a power of two and >= 2 (true here: 128).
// ---------------------------------------------------------------------------
__global__ __launch_bounds__(256)
void bspline_stream2(float* __restrict__ out, int sp_count,
                     int DIM4, int shift2, int total2) {
    const int idx = blockIdx.x * 256 + threadIdx.x;
    if (idx >= total2) return;
    const int half = DIM4 >> 1;
    const int smp  = idx >> shift2;        // sample index
    const int d    = idx & (half - 1);     // first float4 lane

    const float4 w  = g_w4[smp];
    const int    c0 = g_c0[smp];

    const float4* __restrict__ cT4 = reinterpret_cast<const float4*>(g_cT);
    const float4* b = cT4 + (size_t)c0 * DIM4 + d;

    // 8 independent loads (issued back-to-back, MLP=8)
    const float4 a0 = b[0];
    const float4 a1 = b[DIM4];
    const float4 a2 = b[2 * DIM4];
    const float4 a3 = b[3 * DIM4];
    const float4 e0 = b[half];
    const float4 e1 = b[DIM4 + half];
    const float4 e2 = b[2 * DIM4 + half];
    const float4 e3 = b[3 * DIM4 + half];

    float4 r0, r1;
    r0.x = w.x * a0.x + w.y * a1.x + w.z * a2.x + w.w * a3.x;
    r0.y = w.x * a0.y + w.y * a1.y + w.z * a2.y + w.w * a3.y;
    r0.z = w.x * a0.z + w.y * a1.z + w.z * a2.z + w.w * a3.z;
    r0.w = w.x * a0.w + w.y * a1.w + w.z * a2.w + w.w * a3.w;
    r1.x = w.x * e0.x + w.y * e1.x + w.z * e2.x + w.w * e3.x;
    r1.y = w.x * e0.y + w.y * e1.y + w.z * e2.y + w.w * e3.y;
    r1.z = w.x * e0.z + w.y * e1.z + w.z * e2.z + w.w * e3.z;
    r1.w = w.x * e0.w + w.y * e1.w + w.z * e2.w + w.w * e3.w;

    float4* o = reinterpret_cast<float4*>(out + sp_count) + (size_t)smp * DIM4 + d;
    o[0]    = r0;
    o[half] = r1;
}

// ---------------------------------------------------------------------------
// Kernel 3 (scalar fallback): one thread per output element. Shape-safe.
// ---------------------------------------------------------------------------
__global__ __launch_bounds__(256)
void bspline_stream_scalar(float* __restrict__ out, int sp_count,
                           int DIM, long long total) {
    const long long idx = (long long)blockIdx.x * 256 + threadIdx.x;
    if (idx >= total) return;
    const int smp = (int)(idx / DIM);
    const int d   = (int)(idx - (long long)smp * DIM);
    const float4 w  = g_w4[smp];
    const int    c0 = g_c0[smp];
    float r = w.x * g_cT[(size_t)(c0 + 0) * DIM + d]
            + w.y * g_cT[(size_t)(c0 + 1) * DIM + d]
            + w.z * g_cT[(size_t)(c0 + 2) * DIM + d]
            + w.w * g_cT[(size_t)(c0 + 3) * DIM + d];
    out[(size_t)sp_count + (size_t)smp * DIM + d] = r;
}

// ---------------------------------------------------------------------------
extern "C" void kernel_launch(void* const* d_in, const int* in_sizes, int n_in,
                              void* d_out, int out_size) {
    const float* t     = (const float*)d_in[0];
    const float* c     = (const float*)d_in[1];
    const int*   delta = (const int*)d_in[2];
    float*       out   = (float*)d_out;

    const int NK  = in_sizes[0];        // 2048
    const int DIM = in_sizes[1] / NK;   // 512

    // Output = concat(sample_points[S], spline[S, DIM]) -> out_size = S*(DIM+1).
    int S, sp_count;
    if (out_size % (DIM + 1) == 0) { S = out_size / (DIM + 1); sp_count = S; }
    else                           { S = out_size / DIM;       sp_count = 0; }

    // K1: transpose c into knot-major scratch
    dim3 tb(32, 8);
    dim3 tg((NK + 31) / 32, (DIM + 31) / 32);
    bspline_transpose<<<tg, tb>>>(c, DIM, NK);

    // K2: per-sample span + weights (fully parallel)
    bspline_weights<<<(S + 255) / 256, 256>>>(t, delta, out, NK, S, sp_count);

    // K3: streaming weighted sum
    const int DIM4 = DIM >> 2;
    const bool pow2 = (DIM4 >= 2) && ((DIM4 & (DIM4 - 1)) == 0);
    const bool vec  = ((DIM & 7) == 0) && ((sp_count & 3) == 0) && pow2
                      && (S <= S_CAP);
    if (vec) {
        int shift2 = 0;
        { int h = DIM4 >> 1; while ((1 << shift2) < h) shift2++; }  // log2(DIM4/2)
        const int total2 = S * (DIM4 >> 1);
        bspline_stream2<<<(total2 + 255) / 256, 256>>>(out, sp_count, DIM4,
                                                       shift2, total2);
    } else {
        const long long total = (long long)S * DIM;
        bspline_stream_scalar<<<(int)((total + 255) / 256), 256>>>(out, sp_count,
                                                                   DIM, total);
    }
}

// round 9
// speedup vs baseline: 1.1633x; 1.1633x over previous
#include <cuda_runtime.h>

// Problem-instance capacities. Scratch is __device__ global (allocation-guard safe).
#define NK_CAP  2048
#define DIM_CAP 512
#define S_CAP   131072

__device__ float  g_cT[(size_t)NK_CAP * DIM_CAP];  // c transposed: [NK][DIM], 4 MB
__device__ float4 g_w4[S_CAP];                     // per-sample weights
__device__ int    g_c0[S_CAP];                     // per-sample first column

typedef unsigned long long ull;

// ---- packed f32x2 helpers (sm_100+/sm_103a) ----
__device__ __forceinline__ ull fma2(ull a, ull b, ull c) {
    ull d; asm("fma.rn.f32x2 %0, %1, %2, %3;" : "=l"(d) : "l"(a), "l"(b), "l"(c));
    return d;
}
__device__ __forceinline__ ull mul2(ull a, ull b) {
    ull d; asm("mul.rn.f32x2 %0, %1, %2;" : "=l"(d) : "l"(a), "l"(b));
    return d;
}
__device__ __forceinline__ ull dup2(float x) {
    ull d; unsigned xi = __float_as_uint(x);
    asm("mov.b64 %0, {%1, %2};" : "=l"(d) : "r"(xi), "r"(xi));
    return d;
}

// ---------------------------------------------------------------------------
// Kernel 1: transpose c[DIM][NK] -> g_cT[NK][DIM] (tiled, conflict-free)
// ---------------------------------------------------------------------------
__global__ void bspline_transpose(const float* __restrict__ c, int DIM, int NK) {
    __shared__ float tile[32][33];
    const int x  = blockIdx.x * 32 + threadIdx.x;  // knot index (c column)
    const int y0 = blockIdx.y * 32;                // dim base   (c row)
    #pragma unroll
    for (int i = threadIdx.y; i < 32; i += 8) {
        int y = y0 + i;
        if (x < NK && y < DIM)
            tile[i][threadIdx.x] = c[(size_t)y * NK + x];
    }
    __syncthreads();
    const int xd  = y0 + threadIdx.x;              // dim index (cT column)
    const int yk0 = blockIdx.x * 32;               // knot base (cT row)
    #pragma unroll
    for (int i = threadIdx.y; i < 32; i += 8) {
        int yk = yk0 + i;
        if (xd < DIM && yk < NK)
            g_cT[(size_t)yk * DIM + xd] = tile[threadIdx.x][i];
    }
}

// ---------------------------------------------------------------------------
// Kernel 2: one thread per sample — binary search + 4 Cox-de Boor weights.
// Faithful to the reference's truncated in-place recursion:
//   final row F[i] = B3[i] (i < NK-3), B2[NK-3], B1[NK-2], B0[NK-1];
//   samples beyond the last proper span give an all-zero row; denom==0 -> 0.
// ---------------------------------------------------------------------------
__global__ __launch_bounds__(256)
void bspline_weights(const float* __restrict__ t,
                     const int*   __restrict__ delta_raw,
                     float* __restrict__ out,
                     int NK, int S, int sp_count) {
    const int sidx = blockIdx.x * 256 + threadIdx.x;
    if (sidx >= S || sidx >= S_CAP) return;

    // delta arrives as int32 (python int); tolerate float32 encoding too.
    int iv = *delta_raw;
    float delta = (iv > 0 && iv < (1 << 20)) ? (float)iv : __int_as_float(iv);

    const float s = (float)sidx * delta;
    if (sp_count) out[sidx] = s;  // sample_points region

    float w0 = 0.f, w1 = 0.f, w2 = 0.f, w3 = 0.f;
    int c0 = 0;

    // ub = first index with t[ub] > s  (span j = ub + 3 in padded knots)
    int lo = 0, hi = NK;
    while (lo < hi) {
        int mid = (lo + hi) >> 1;
        if (__ldg(&t[mid]) > s) hi = mid; else lo = mid + 1;
    }
    const int ub = lo;
    if (ub <= NK - 4) {
        const int j = ub + 3;  // padded-knot span: k[j] <= s < k[j+1]
        float k[8];
        #pragma unroll
        for (int m = 1; m <= 6; m++) {
            int gi = j - 3 + m;
            k[m] = (gi < 4) ? 0.0f : __ldg(&t[gi - 4]);
        }
        const float Km2 = k[1], Km1 = k[2], K0 = k[3];
        const float K1  = k[4], K2  = k[5], K3 = k[6];

        auto rat = [](float num, float den) -> float {
            return (den == 0.0f) ? 0.0f : num / den;
        };

        // degree 1
        const float b1a = rat(K1 - s, K1 - K0);
        const float b1b = rat(s - K0, K1 - K0);
        // degree 2
        const float b2a = rat(K1 - s, K1 - Km1) * b1a;
        const float b2b = rat(s - Km1, K1 - Km1) * b1a
                        + rat(K2 - s, K2 - K0)   * b1b;
        const float b2c = rat(s - K0, K2 - K0)   * b1b;
        // degree 3
        const float b3a = rat(K1 - s, K1 - Km2) * b2a;
        const float b3b = rat(s - Km2, K1 - Km2) * b2a
                        + rat(K2 - s, K2 - Km1)  * b2b;
        const float b3c = rat(s - Km1, K2 - Km1) * b2b
                        + rat(K3 - s, K3 - K0)   * b2c;
        const float b3d = rat(s - K0, K3 - K0)   * b2c;

        const float b3v[4] = {b3a, b3b, b3c, b3d};
        const float b2v[3] = {b2a, b2b, b2c};
        const float b1v[2] = {b1a, b1b};
        float wv[4];
        #pragma unroll
        for (int m = 0; m < 4; m++) {
            const int col = j - 3 + m;
            float f = b3v[m];                                    // proper deg-3
            if (col == NK - 3)      f = b2v[m > 0 ? m - 1 : 0];  // stale deg-2
            else if (col == NK - 2) f = b1v[m > 1 ? m - 2 : 0];  // stale deg-1
            else if (col == NK - 1) f = 1.0f;                    // stale deg-0
            wv[m] = f;
        }
        w0 = wv[0]; w1 = wv[1]; w2 = wv[2]; w3 = wv[3];
        c0 = j - 3;
    }
    g_w4[sidx] = make_float4(w0, w1, w2, w3);
    g_c0[sidx] = c0;
}

// ---------------------------------------------------------------------------
// Kernel 3 (fast path): fused epilogue with REGISTER row-caching.
// Block = DIM4 threads, each owning one float4 output lane. Block iterates
// SPB consecutive samples; c0 is non-decreasing and uniform across the block,
// so on span changes we shift the 4 cached rows and load only the new one(s).
// Math in packed f32x2 FMAs (halves FFMA instruction count).
// ---------------------------------------------------------------------------
#define SPB 64

__global__ __launch_bounds__(1024)
void bspline_fused(float* __restrict__ out, int sp_count, int DIM4, int S) {
    __shared__ float4 sw[SPB];
    __shared__ int    sc[SPB];

    const int tid = threadIdx.x;
    const int s0  = blockIdx.x * SPB;

    if (tid < SPB) {
        const int s = s0 + tid;
        if (s < S) { sw[tid] = g_w4[s]; sc[tid] = g_c0[s]; }
        else       { sw[tid] = make_float4(0.f, 0.f, 0.f, 0.f); sc[tid] = 0; }
    }
    __syncthreads();

    const int nS = (S - s0 < SPB) ? (S - s0) : SPB;
    const ulonglong2* __restrict__ cTu =
        reinterpret_cast<const ulonglong2*>(g_cT);
    ulonglong2* __restrict__ o =
        reinterpret_cast<ulonglong2*>(out + sp_count) + (size_t)s0 * DIM4 + tid;

    int cur = -0x40000000;           // invalid => force full reload
    ulonglong2 v0, v1, v2, v3;       // cached rows c0..c0+3 at this lane

    #pragma unroll 1
    for (int i = 0; i < nS; i++) {
        const int    c0 = sc[i];
        const float4 w  = sw[i];
        const int    dl = c0 - cur;
        if (dl != 0) {
            const ulonglong2* b = cTu + (size_t)c0 * DIM4 + tid;
            if (dl == 1)      { v0 = v1; v1 = v2; v2 = v3; v3 = b[3 * DIM4]; }
            else if (dl == 2) { v0 = v2; v1 = v3; v2 = b[2 * DIM4]; v3 = b[3 * DIM4]; }
            else if (dl == 3) { v0 = v3; v1 = b[DIM4]; v2 = b[2 * DIM4]; v3 = b[3 * DIM4]; }
            else              { v0 = b[0]; v1 = b[DIM4]; v2 = b[2 * DIM4]; v3 = b[3 * DIM4]; }
            cur = c0;
        }
        const ull wx = dup2(w.x), wy = dup2(w.y), wz = dup2(w.z), ww = dup2(w.w);
        ulonglong2 acc;
        acc.x = fma2(wx, v0.x, fma2(wy, v1.x, fma2(wz, v2.x, mul2(ww, v3.x))));
        acc.y = fma2(wx, v0.y, fma2(wy, v1.y, fma2(wz, v2.y, mul2(ww, v3.y))));
        o[(size_t)i * DIM4] = acc;
    }
}

// ---------------------------------------------------------------------------
// Scalar fallback: one thread per output element. Shape-safe.
// ---------------------------------------------------------------------------
__global__ __launch_bounds__(256)
void bspline_stream_scalar(float* __restrict__ out, int sp_count,
                           int DIM, long long total) {
    const long long idx = (long long)blockIdx.x * 256 + threadIdx.x;
    if (idx >= total) return;
    const int smp = (int)(idx / DIM);
    const int d   = (int)(idx - (long long)smp * DIM);
    const float4 w  = g_w4[smp];
    const int    c0 = g_c0[smp];
    float r = w.x * g_cT[(size_t)(c0 + 0) * DIM + d]
            + w.y * g_cT[(size_t)(c0 + 1) * DIM + d]
            + w.z * g_cT[(size_t)(c0 + 2) * DIM + d]
            + w.w * g_cT[(size_t)(c0 + 3) * DIM + d];
    out[(size_t)sp_count + (size_t)smp * DIM + d] = r;
}

// ---------------------------------------------------------------------------
extern "C" void kernel_launch(void* const* d_in, const int* in_sizes, int n_in,
                              void* d_out, int out_size) {
    const float* t     = (const float*)d_in[0];
    const float* c     = (const float*)d_in[1];
    const int*   delta = (const int*)d_in[2];
    float*       out   = (float*)d_out;

    const int NK  = in_sizes[0];        // 2048
    const int DIM = in_sizes[1] / NK;   // 512

    // Output = concat(sample_points[S], spline[S, DIM]) -> out_size = S*(DIM+1).
    int S, sp_count;
    if (out_size % (DIM + 1) == 0) { S = out_size / (DIM + 1); sp_count = S; }
    else                           { S = out_size / DIM;       sp_count = 0; }

    // K1: transpose c into knot-major scratch
    dim3 tb(32, 8);
    dim3 tg((NK + 31) / 32, (DIM + 31) / 32);
    bspline_transpose<<<tg, tb>>>(c, DIM, NK);

    // K2: per-sample span + weights (fully parallel)
    bspline_weights<<<(S + 255) / 256, 256>>>(t, delta, out, NK, S, sp_count);

    // K3: fused register-cached epilogue
    const int DIM4 = DIM >> 2;
    const bool vec = ((DIM & 7) == 0) && ((sp_count & 3) == 0) &&
                     (DIM4 >= 32) && (DIM4 <= 1024) && (S <= S_CAP);
    if (vec) {
        const int grid = (S + SPB - 1) / SPB;
        bspline_fused<<<grid, DIM4>>>(out, sp_count, DIM4, S);
    } else {
        const long long total = (long long)S * DIM;
        bspline_stream_scalar<<<(int)((total + 255) / 256), 256>>>(out, sp_count,
                                                                   DIM, total);
    }
}

// round 10
// speedup vs baseline: 1.3902x; 1.1951x over previous
#include <cuda_runtime.h>

// Problem-instance capacities. Scratch is __device__ global (allocation-guard safe).
#define NK_CAP  2048
#define DIM_CAP 512
#define S_CAP   131072

__device__ float      g_cT[(size_t)NK_CAP * DIM_CAP];  // c transposed: [NK][DIM]
__device__ float4     g_w4[S_CAP];                     // per-sample weights (fallback path)
__device__ ulonglong2 g_wp[S_CAP][2];                  // pre-duplicated packed f32x2 weights
__device__ int        g_c0[S_CAP];                     // per-sample first column

typedef unsigned long long ull;

// ---- packed f32x2 helpers (sm_103a) ----
__device__ __forceinline__ ull fma2(ull a, ull b, ull c) {
    ull d; asm("fma.rn.f32x2 %0, %1, %2, %3;" : "=l"(d) : "l"(a), "l"(b), "l"(c));
    return d;
}
__device__ __forceinline__ ull mul2(ull a, ull b) {
    ull d; asm("mul.rn.f32x2 %0, %1, %2;" : "=l"(d) : "l"(a), "l"(b));
    return d;
}
__device__ __forceinline__ ull dup2(float x) {
    ull d; unsigned xi = __float_as_uint(x);
    asm("mov.b64 %0, {%1, %2};" : "=l"(d) : "r"(xi), "r"(xi));
    return d;
}

// ---------------------------------------------------------------------------
// Kernel A (block-specialized): transpose + per-sample weights, concurrently.
//   blocks [0, TB)        : tiled transpose c[DIM][NK] -> g_cT[NK][DIM]
//                           (two 32x32 tiles per block -> 8-deep load MLP)
//   blocks [TB, TB+WB)    : one thread per sample: binary search + Cox-de Boor
// Weight semantics are faithful to the reference's truncated in-place
// recursion: final row F[i] = B3[i] (i < NK-3), B2[NK-3], B1[NK-2], B0[NK-1];
// samples beyond the last proper span -> all-zero row; denom==0 -> weight 0.
// ---------------------------------------------------------------------------
__global__ __launch_bounds__(256)
void bspline_prep(const float* __restrict__ c,
                  const float* __restrict__ t,
                  const int*   __restrict__ delta_raw,
                  float* __restrict__ out,
                  int DIM, int NK, int S, int sp_count,
                  int TB, int TBx) {
    const int bid = blockIdx.x;
    if (bid < TB) {
        // ---------------- transpose role ----------------
        __shared__ float tile[2][32][33];
        const int bx = bid % TBx, by = bid / TBx;
        const int x0 = bx * 64, y0 = by * 32;
        const int tx = threadIdx.x & 31;
        const int ty = threadIdx.x >> 5;   // 0..7
        #pragma unroll
        for (int h = 0; h < 2; h++) {
            const int x = x0 + h * 32 + tx;
            #pragma unroll
            for (int i = ty; i < 32; i += 8) {
                const int y = y0 + i;
                if (x < NK && y < DIM)
                    tile[h][i][tx] = c[(size_t)y * NK + x];
            }
        }
        __syncthreads();
        #pragma unroll
        for (int h = 0; h < 2; h++) {
            const int xd = y0 + tx;
            #pragma unroll
            for (int i = ty; i < 32; i += 8) {
                const int yk = x0 + h * 32 + i;
                if (xd < DIM && yk < NK)
                    g_cT[(size_t)yk * DIM + xd] = tile[h][tx][i];
            }
        }
        return;
    }

    // ---------------- weights role ----------------
    const int sidx = (bid - TB) * 256 + threadIdx.x;
    if (sidx >= S || sidx >= S_CAP) return;

    // delta arrives as int32 (python int); tolerate float32 encoding too.
    int iv = *delta_raw;
    float delta = (iv > 0 && iv < (1 << 20)) ? (float)iv : __int_as_float(iv);

    const float s = (float)sidx * delta;
    if (sp_count) out[sidx] = s;  // sample_points region

    float w0 = 0.f, w1 = 0.f, w2 = 0.f, w3 = 0.f;
    int c0 = 0;

    // ub = first index with t[ub] > s  (span j = ub + 3 in padded knots)
    int lo = 0, hi = NK;
    while (lo < hi) {
        int mid = (lo + hi) >> 1;
        if (__ldg(&t[mid]) > s) hi = mid; else lo = mid + 1;
    }
    const int ub = lo;
    if (ub <= NK - 4) {
        const int j = ub + 3;  // padded-knot span: k[j] <= s < k[j+1]
        float k[8];
        #pragma unroll
        for (int m = 1; m <= 6; m++) {
            int gi = j - 3 + m;
            k[m] = (gi < 4) ? 0.0f : __ldg(&t[gi - 4]);
        }
        const float Km2 = k[1], Km1 = k[2], K0 = k[3];
        const float K1  = k[4], K2  = k[5], K3 = k[6];

        auto rat = [](float num, float den) -> float {
            return (den == 0.0f) ? 0.0f : num / den;
        };

        // degree 1
        const float b1a = rat(K1 - s, K1 - K0);
        const float b1b = rat(s - K0, K1 - K0);
        // degree 2
        const float b2a = rat(K1 - s, K1 - Km1) * b1a;
        const float b2b = rat(s - Km1, K1 - Km1) * b1a
                        + rat(K2 - s, K2 - K0)   * b1b;
        const float b2c = rat(s - K0, K2 - K0)   * b1b;
        // degree 3
        const float b3a = rat(K1 - s, K1 - Km2) * b2a;
        const float b3b = rat(s - Km2, K1 - Km2) * b2a
                        + rat(K2 - s, K2 - Km1)  * b2b;
        const float b3c = rat(s - Km1, K2 - Km1) * b2b
                        + rat(K3 - s, K3 - K0)   * b2c;
        const float b3d = rat(s - K0, K3 - K0)   * b2c;

        const float b3v[4] = {b3a, b3b, b3c, b3d};
        const float b2v[3] = {b2a, b2b, b2c};
        const float b1v[2] = {b1a, b1b};
        float wv[4];
        #pragma unroll
        for (int m = 0; m < 4; m++) {
            const int col = j - 3 + m;
            float f = b3v[m];                                    // proper deg-3
            if (col == NK - 3)      f = b2v[m > 0 ? m - 1 : 0];  // stale deg-2
            else if (col == NK - 2) f = b1v[m > 1 ? m - 2 : 0];  // stale deg-1
            else if (col == NK - 1) f = 1.0f;                    // stale deg-0
            wv[m] = f;
        }
        w0 = wv[0]; w1 = wv[1]; w2 = wv[2]; w3 = wv[3];
        c0 = j - 3;
    }
    g_w4[sidx] = make_float4(w0, w1, w2, w3);
    ulonglong2 p0; p0.x = dup2(w0); p0.y = dup2(w1);
    ulonglong2 p1; p1.x = dup2(w2); p1.y = dup2(w3);
    g_wp[sidx][0] = p0;
    g_wp[sidx][1] = p1;
    g_c0[sidx] = c0;
}

// ---------------------------------------------------------------------------
// Kernel B (fast path): fused epilogue with REGISTER row-caching.
// Block = DIM4 threads, each owning one float4 output lane; SPB=16 samples
// per block for high occupancy. c0 is non-decreasing and uniform across the
// block: on +1 steps shift the 4 cached rows and load one; otherwise reload.
// Math in packed f32x2 FMAs with pre-duplicated weights.
// ---------------------------------------------------------------------------
#define SPB 16

__global__ __launch_bounds__(1024)
void bspline_fused(float* __restrict__ out, int sp_count, int DIM4, int S) {
    __shared__ ulonglong2 swp[SPB][2];
    __shared__ int        sc[SPB];

    const int tid = threadIdx.x;
    const int s0  = blockIdx.x * SPB;

    if (tid < 2 * SPB) {
        const int sm = tid >> 1, half = tid & 1;
        const int s  = s0 + sm;
        swp[sm][half] = (s < S) ? g_wp[s][half]
                                : make_ulonglong2(0ull, 0ull);
    }
    if (tid < SPB) {
        const int s = s0 + tid;
        sc[tid] = (s < S) ? g_c0[s] : 0;
    }
    __syncthreads();

    const int nS = (S - s0 < SPB) ? (S - s0) : SPB;
    const ulonglong2* __restrict__ cTu =
        reinterpret_cast<const ulonglong2*>(g_cT);
    ulonglong2* __restrict__ o =
        reinterpret_cast<ulonglong2*>(out + sp_count) + (size_t)s0 * DIM4 + tid;

    int cur = -0x40000000;           // invalid => force full reload
    ulonglong2 v0, v1, v2, v3;       // cached rows c0..c0+3 at this lane

    #pragma unroll 1
    for (int i = 0; i < nS; i++) {
        const int c0 = sc[i];
        if (c0 != cur) {
            const ulonglong2* b = cTu + (size_t)c0 * DIM4 + tid;
            if (c0 == cur + 1) {               // common: step by one span
                v0 = v1; v1 = v2; v2 = v3; v3 = b[3 * DIM4];
            } else {                           // first iter / multi-step
                v0 = b[0]; v1 = b[DIM4]; v2 = b[2 * DIM4]; v3 = b[3 * DIM4];
            }
            cur = c0;
        }
        const ulonglong2 wA = swp[i][0];
        const ulonglong2 wB = swp[i][1];
        ulonglong2 acc;
        acc.x = fma2(wA.x, v0.x, fma2(wA.y, v1.x, fma2(wB.x, v2.x, mul2(wB.y, v3.x))));
        acc.y = fma2(wA.x, v0.y, fma2(wA.y, v1.y, fma2(wB.x, v2.y, mul2(wB.y, v3.y))));
        o[(size_t)i * DIM4] = acc;
    }
}

// ---------------------------------------------------------------------------
// Scalar fallback: one thread per output element. Shape-safe.
// ---------------------------------------------------------------------------
__global__ __launch_bounds__(256)
void bspline_stream_scalar(float* __restrict__ out, int sp_count,
                           int DIM, long long total) {
    const long long idx = (long long)blockIdx.x * 256 + threadIdx.x;
    if (idx >= total) return;
    const int smp = (int)(idx / DIM);
    const int d   = (int)(idx - (long long)smp * DIM);
    const float4 w  = g_w4[smp];
    const int    c0 = g_c0[smp];
    float r = w.x * g_cT[(size_t)(c0 + 0) * DIM + d]
            + w.y * g_cT[(size_t)(c0 + 1) * DIM + d]
            + w.z * g_cT[(size_t)(c0 + 2) * DIM + d]
            + w.w * g_cT[(size_t)(c0 + 3) * DIM + d];
    out[(size_t)sp_count + (size_t)smp * DIM + d] = r;
}

// ---------------------------------------------------------------------------
extern "C" void kernel_launch(void* const* d_in, const int* in_sizes, int n_in,
                              void* d_out, int out_size) {
    const float* t     = (const float*)d_in[0];
    const float* c     = (const float*)d_in[1];
    const int*   delta = (const int*)d_in[2];
    float*       out   = (float*)d_out;

    const int NK  = in_sizes[0];        // 2048
    const int DIM = in_sizes[1] / NK;   // 512

    // Output = concat(sample_points[S], spline[S, DIM]) -> out_size = S*(DIM+1).
    int S, sp_count;
    if (out_size % (DIM + 1) == 0) { S = out_size / (DIM + 1); sp_count = S; }
    else                           { S = out_size / DIM;       sp_count = 0; }

    // Kernel A: transpose + weights in one launch (independent roles overlap)
    const int TBx = (NK + 63) / 64;
    const int TBy = (DIM + 31) / 32;
    const int TB  = TBx * TBy;
    const int WB  = (S + 255) / 256;
    bspline_prep<<<TB + WB, 256>>>(c, t, delta, out, DIM, NK, S, sp_count,
                                   TB, TBx);

    // Kernel B: fused register-cached epilogue
    const int DIM4 = DIM >> 2;
    const bool vec = ((DIM & 7) == 0) && ((sp_count & 3) == 0) &&
                     (DIM4 >= 32) && (DIM4 <= 1024) && (S <= S_CAP);
    if (vec) {
        const int grid = (S + SPB - 1) / SPB;
        bspline_fused<<<grid, DIM4>>>(out, sp_count, DIM4, S);
    } else {
        const long long total = (long long)S * DIM;
        bspline_stream_scalar<<<(int)((total + 255) / 256), 256>>>(out, sp_count,
                                                                   DIM, total);
    }
}

// round 13
// speedup vs baseline: 1.3945x; 1.0031x over previous
#include <cuda_runtime.h>

// Problem-instance capacities. Scratch is __device__ global (allocation-guard safe).
#define NK_CAP  2048
#define DIM_CAP 512
#define S_CAP   131072

__device__ float      g_cT[(size_t)NK_CAP * DIM_CAP];  // c transposed: [NK][DIM]
__device__ float4     g_w4[S_CAP];                     // per-sample weights (fallback path)
__device__ ulonglong2 g_wp[S_CAP][2];                  // pre-duplicated packed f32x2 weights
__device__ int        g_c0[S_CAP];                     // per-sample first column

typedef unsigned long long ull;

// ---- packed f32x2 helpers (sm_103a) ----
__device__ __forceinline__ ull fma2(ull a, ull b, ull c) {
    ull d; asm("fma.rn.f32x2 %0, %1, %2, %3;" : "=l"(d) : "l"(a), "l"(b), "l"(c));
    return d;
}
__device__ __forceinline__ ull mul2(ull a, ull b) {
    ull d; asm("mul.rn.f32x2 %0, %1, %2;" : "=l"(d) : "l"(a), "l"(b));
    return d;
}
__device__ __forceinline__ ull dup2(float x) {
    ull d; unsigned xi = __float_as_uint(x);
    asm("mov.b64 %0, {%1, %2};" : "=l"(d) : "r"(xi), "r"(xi));
    return d;
}

// ---------------------------------------------------------------------------
// Kernel A (block-specialized): transpose + per-sample weights, concurrently.
//   blocks [0, TB)     : transpose c[DIM][NK] -> g_cT[NK][DIM] with float4
//                        global reads (64-knot x 32-dim tiles)
//   blocks [TB, TB+WB) : one thread per sample: binary search + Cox-de Boor
// Weight semantics faithful to the reference's truncated in-place recursion:
//   final row F[i] = B3[i] (i < NK-3), B2[NK-3], B1[NK-2], B0[NK-1];
//   samples beyond the last proper span -> all-zero row; denom==0 -> weight 0.
// ---------------------------------------------------------------------------
__global__ __launch_bounds__(256)
void bspline_prep(const float* __restrict__ c,
                  const float* __restrict__ t,
                  const int*   __restrict__ delta_raw,
                  float* __restrict__ out,
                  int DIM, int NK, int S, int sp_count,
                  int TB, int TBx) {
    const int bid = blockIdx.x;
    if (bid < TB) {
        // ---------------- transpose role ----------------
        __shared__ float tile[64][33];   // [knot_local][dim_local], 2-way max
        const int bx = bid % TBx, by = bid / TBx;
        const int x0 = bx * 64, y0 = by * 32;
        const int ltx = threadIdx.x & 15;   // knot quad index
        const int lty = threadIdx.x >> 4;   // 0..15 dim index
        const bool v4ok = ((NK & 3) == 0);
        #pragma unroll
        for (int q = 0; q < 2; q++) {
            const int y = y0 + lty + 16 * q;   // dim
            const int x = x0 + 4 * ltx;        // knot
            if (y < DIM) {
                if (v4ok && x + 3 < NK) {
                    const float4 v = *reinterpret_cast<const float4*>(
                        &c[(size_t)y * NK + x]);
                    tile[4 * ltx + 0][lty + 16 * q] = v.x;
                    tile[4 * ltx + 1][lty + 16 * q] = v.y;
                    tile[4 * ltx + 2][lty + 16 * q] = v.z;
                    tile[4 * ltx + 3][lty + 16 * q] = v.w;
                } else {
                    #pragma unroll
                    for (int j = 0; j < 4; j++)
                        if (x + j < NK)
                            tile[4 * ltx + j][lty + 16 * q] =
                                c[(size_t)y * NK + x + j];
                }
            }
        }
        __syncthreads();
        const int wtx = threadIdx.x & 31;   // dim
        const int wty = threadIdx.x >> 5;   // 0..7
        const int xd = y0 + wtx;
        if (xd < DIM) {
            #pragma unroll
            for (int i = wty; i < 64; i += 8) {
                const int yk = x0 + i;
                if (yk < NK)
                    g_cT[(size_t)yk * DIM + xd] = tile[i][wtx];
            }
        }
        return;
    }

    // ---------------- weights role ----------------
    const int sidx = (bid - TB) * 256 + threadIdx.x;
    if (sidx >= S || sidx >= S_CAP) return;

    // delta arrives as int32 (python int); tolerate float32 encoding too.
    int iv = *delta_raw;
    float delta = (iv > 0 && iv < (1 << 20)) ? (float)iv : __int_as_float(iv);

    const float s = (float)sidx * delta;
    if (sp_count) out[sidx] = s;  // sample_points region

    float w0 = 0.f, w1 = 0.f, w2 = 0.f, w3 = 0.f;
    int c0 = 0;

    // ub = first index with t[ub] > s  (span j = ub + 3 in padded knots)
    int lo = 0, hi = NK;
    while (lo < hi) {
        int mid = (lo + hi) >> 1;
        if (__ldg(&t[mid]) > s) hi = mid; else lo = mid + 1;
    }
    const int ub = lo;
    if (ub <= NK - 4) {
        const int j = ub + 3;  // padded-knot span: k[j] <= s < k[j+1]
        float k[8];
        #pragma unroll
        for (int m = 1; m <= 6; m++) {
            int gi = j - 3 + m;
            k[m] = (gi < 4) ? 0.0f : __ldg(&t[gi - 4]);
        }
        const float Km2 = k[1], Km1 = k[2], K0 = k[3];
        const float K1  = k[4], K2  = k[5], K3 = k[6];

        auto rat = [](float num, float den) -> float {
            return (den == 0.0f) ? 0.0f : num / den;
        };

        // degree 1
        const float b1a = rat(K1 - s, K1 - K0);
        const float b1b = rat(s - K0, K1 - K0);
        // degree 2
        const float b2a = rat(K1 - s, K1 - Km1) * b1a;
        const float b2b = rat(s - Km1, K1 - Km1) * b1a
                        + rat(K2 - s, K2 - K0)   * b1b;
        const float b2c = rat(s - K0, K2 - K0)   * b1b;
        // degree 3
        const float b3a = rat(K1 - s, K1 - Km2) * b2a;
        const float b3b = rat(s - Km2, K1 - Km2) * b2a
                        + rat(K2 - s, K2 - Km1)  * b2b;
        const float b3c = rat(s - Km1, K2 - Km1) * b2b
                        + rat(K3 - s, K3 - K0)   * b2c;
        const float b3d = rat(s - K0, K3 - K0)   * b2c;

        const float b3v[4] = {b3a, b3b, b3c, b3d};
        const float b2v[3] = {b2a, b2b, b2c};
        const float b1v[2] = {b1a, b1b};
        float wv[4];
        #pragma unroll
        for (int m = 0; m < 4; m++) {
            const int col = j - 3 + m;
            float f = b3v[m];                                    // proper deg-3
            if (col == NK - 3)      f = b2v[m > 0 ? m - 1 : 0];  // stale deg-2
            else if (col == NK - 2) f = b1v[m > 1 ? m - 2 : 0];  // stale deg-1
            else if (col == NK - 1) f = 1.0f;                    // stale deg-0
            wv[m] = f;
        }
        w0 = wv[0]; w1 = wv[1]; w2 = wv[2]; w3 = wv[3];
        c0 = j - 3;
    }
    g_w4[sidx] = make_float4(w0, w1, w2, w3);
    ulonglong2 p0; p0.x = dup2(w0); p0.y = dup2(w1);
    ulonglong2 p1; p1.x = dup2(w2); p1.y = dup2(w3);
    g_wp[sidx][0] = p0;
    g_wp[sidx][1] = p1;
    g_c0[sidx] = c0;
}

// ---------------------------------------------------------------------------
// Kernel B (fast path): fused epilogue, segment-structured with speculative
// row prefetch. Block = DIM4 threads, one float4 output lane each; SPB=16
// samples per block. Within a span segment the loop is branch-free FMA+STG.
// Register p holds row (cur+4), loaded at each span change and consumed at
// the next one -> boundary load latency hidden behind a span of work.
// Clamp note: the "+1 shift consumes p" path requires c0+4 <= NK-1, so a
// clamped (stale-content) p is never consumed.
// ---------------------------------------------------------------------------
#define SPB 16

__global__ __launch_bounds__(1024)
void bspline_fused(float* __restrict__ out, int sp_count, int DIM4,
                   int S, int NK) {
    __shared__ ulonglong2 swp[SPB][2];
    __shared__ int        sc[SPB];

    const int tid = threadIdx.x;
    const int s0  = blockIdx.x * SPB;

    if (tid < 2 * SPB) {
        const int sm = tid >> 1, half = tid & 1;
        const int s  = s0 + sm;
        swp[sm][half] = (s < S) ? g_wp[s][half]
                                : make_ulonglong2(0ull, 0ull);
    }
    if (tid < SPB) {
        const int s = s0 + tid;
        sc[tid] = (s < S) ? g_c0[s] : 0;
    }
    __syncthreads();

    const int nS = (S - s0 < SPB) ? (S - s0) : SPB;
    const ulonglong2* __restrict__ cTu =
        reinterpret_cast<const ulonglong2*>(g_cT);
    ulonglong2* __restrict__ o =
        reinterpret_cast<ulonglong2*>(out + sp_count) + (size_t)s0 * DIM4 + tid;

    int cur = sc[0];
    {
        // cold start: 4 rows + speculative next row, all issued together (MLP=5)
        const ulonglong2* b = cTu + (size_t)cur * DIM4 + tid;
        ulonglong2 v0 = b[0], v1 = b[DIM4], v2 = b[2 * DIM4], v3 = b[3 * DIM4];
        int pr = cur + 4; if (pr > NK - 1) pr = NK - 1;
        ulonglong2 p = cTu[(size_t)pr * DIM4 + tid];

        int i = 0;
        #pragma unroll 1
        while (i < nS) {
            // find end of current span segment (sc uniform across block)
            int e = i + 1;
            while (e < nS && sc[e] == cur) ++e;
            // branch-free burst over the segment
            #pragma unroll 1
            for (; i < e; ++i) {
                const ulonglong2 wA = swp[i][0];
                const ulonglong2 wB = swp[i][1];
                ulonglong2 acc;
                acc.x = fma2(wA.x, v0.x,
                        fma2(wA.y, v1.x,
                        fma2(wB.x, v2.x, mul2(wB.y, v3.x))));
                acc.y = fma2(wA.x, v0.y,
                        fma2(wA.y, v1.y,
                        fma2(wB.x, v2.y, mul2(wB.y, v3.y))));
                o[(size_t)i * DIM4] = acc;
            }
            if (i < nS) {
                const int cn = sc[i];
                if (cn == cur + 1) {            // common: one-span step
                    v0 = v1; v1 = v2; v2 = v3; v3 = p;
                } else {                        // rare: multi-step / reset
                    const ulonglong2* nb = cTu + (size_t)cn * DIM4 + tid;
                    v0 = nb[0]; v1 = nb[DIM4];
                    v2 = nb[2 * DIM4]; v3 = nb[3 * DIM4];
                }
                cur = cn;
                int pn = cur + 4; if (pn > NK - 1) pn = NK - 1;
                p = cTu[(size_t)pn * DIM4 + tid];  // hidden behind next segment
            }
        }
    }
}

// ---------------------------------------------------------------------------
// Scalar fallback: one thread per output element. Shape-safe.
// ---------------------------------------------------------------------------
__global__ __launch_bounds__(256)
void bspline_stream_scalar(float* __restrict__ out, int sp_count,
                           int DIM, long long total) {
    const long long idx = (long long)blockIdx.x * 256 + threadIdx.x;
    if (idx >= total) return;
    const int smp = (int)(idx / DIM);
    const int d   = (int)(idx - (long long)smp * DIM);
    const float4 w  = g_w4[smp];
    const int    c0 = g_c0[smp];
    float r = w.x * g_cT[(size_t)(c0 + 0) * DIM + d]
            + w.y * g_cT[(size_t)(c0 + 1) * DIM + d]
            + w.z * g_cT[(size_t)(c0 + 2) * DIM + d]
            + w.w * g_cT[(size_t)(c0 + 3) * DIM + d];
    out[(size_t)sp_count + (size_t)smp * DIM + d] = r;
}

// ---------------------------------------------------------------------------
extern "C" void kernel_launch(void* const* d_in, const int* in_sizes, int n_in,
                              void* d_out, int out_size) {
    const float* t     = (const float*)d_in[0];
    const float* c     = (const float*)d_in[1];
    const int*   delta = (const int*)d_in[2];
    float*       out   = (float*)d_out;

    const int NK  = in_sizes[0];        // 2048
    const int DIM = in_sizes[1] / NK;   // 512

    // Output = concat(sample_points[S], spline[S, DIM]) -> out_size = S*(DIM+1).
    int S, sp_count;
    if (out_size % (DIM + 1) == 0) { S = out_size / (DIM + 1); sp_count = S; }
    else                           { S = out_size / DIM;       sp_count = 0; }

    // Kernel A: transpose + weights in one launch (independent roles overlap)
    const int TBx = (NK + 63) / 64;
    const int TBy = (DIM + 31) / 32;
    const int TB  = TBx * TBy;
    const int WB  = (S + 255) / 256;
    bspline_prep<<<TB + WB, 256>>>(c, t, delta, out, DIM, NK, S, sp_count,
                                   TB, TBx);

    // Kernel B: fused register-cached epilogue with prefetch
    const int DIM4 = DIM >> 2;
    const bool vec = ((DIM & 7) == 0) && ((sp_count & 3) == 0) &&
                     (DIM4 >= 32) && (DIM4 <= 1024) && (S <= S_CAP);
    if (vec) {
        const int grid = (S + SPB - 1) / SPB;
        bspline_fused<<<grid, DIM4>>>(out, sp_count, DIM4, S, NK);
    } else {
        const long long total = (long long)S * DIM;
        bspline_stream_scalar<<<(int)((total + 255) / 256), 256>>>(out, sp_count,
                                                                   DIM, total);
    }
}